// round 14
// baseline (speedup 1.0000x reference)
#include <cuda_runtime.h>
#include <float.h>
#include <math.h>

#define MAXT 8192
#define NB   128          // direction bins (K2 grid)
#define NSL  256          // key slices (K1 grid), 32 rows each
#define RPS  32           // rows per slice
#define CAP  128          // max key candidates per bin (expect ~2-10)
#define CAPQ 320          // max queries per bin list (expect ~64; exact fallback)
#define HOTMAX 16         // max hot slices cached in smem (expect 1-4; fallback)
#define PD   36
#define K1TH 128
#define K2TH 512

// Device scratch (graph-capturable: no allocs). g_qcnt self-resets (K2
// zeroes its own bins at the end; zero-initialized at load). All other
// arrays are fully rewritten by K1 each launch before K2 reads them.
// Stale qlist entries beyond qcnt are never used (loads of them are safe).
__device__ ulonglong2 g_QQ[MAXT], g_KK[MAXT];
__device__ unsigned g_binPS[MAXT];
__device__ float g_Vop[MAXT], g_Varg[MAXT], g_Vstk[MAXT];
__device__ float g_sPartP[NB * NSL], g_sPartS[NB * NSL];  // [bin*NSL + slice]
__device__ float g_n2P[NSL], g_n2S[NSL];                  // per-slice |k|^2 max
__device__ int g_qcnt[2 * NB];
__device__ int g_qlistP[NB * CAPQ], g_qlistS[NB * CAPQ];

__device__ __forceinline__ unsigned long long packf2(float lo, float hi) {
    return ((unsigned long long)__float_as_uint(hi) << 32) | (unsigned long long)__float_as_uint(lo);
}
__device__ __forceinline__ float lo32(unsigned long long v) { return __uint_as_float((unsigned)v); }
__device__ __forceinline__ float hi32(unsigned long long v) { return __uint_as_float((unsigned)(v >> 32)); }

// sm_103a packed fp32 pair math (PTX-only; per-lane rounding == scalar rn).
__device__ __forceinline__ unsigned long long mul2(unsigned long long a, unsigned long long b) {
    unsigned long long r;
    asm("mul.rn.f32x2 %0, %1, %2;" : "=l"(r) : "l"(a), "l"(b));
    return r;
}
__device__ __forceinline__ unsigned long long fma2(unsigned long long a, unsigned long long b, unsigned long long c) {
    unsigned long long r;
    asm("fma.rn.f32x2 %0, %1, %2, %3;" : "=l"(r) : "l"(a), "l"(b), "l"(c));
    return r;
}

__device__ __forceinline__ ulonglong2 ldcg_u2(const ulonglong2* p) {
    uint4 v = __ldcg((const uint4*)p);
    ulonglong2 r;
    r.x = ((unsigned long long)v.y << 32) | v.x;
    r.y = ((unsigned long long)v.w << 32) | v.z;
    return r;
}

#define PI_F 3.14159265358979f
#define TWO_PI_F 6.2831853071795865f

__device__ __forceinline__ unsigned qbins(float qpx, float qpy, float qsx, float qsy) {
    const float SC = NB / TWO_PI_F;
    int bP = (int)((atan2f(qpy, qpx) + PI_F) * SC);
    bP = min(max(bP, 0), NB - 1);
    int bS = (int)((atan2f(qsy, qsx) + PI_F) * SC);
    bS = min(max(bS, 0), NB - 1);
    return (unsigned)bP | ((unsigned)bS << 16);
}

__device__ __forceinline__ void push_query(int i, unsigned bp) {
    const int bP = (int)(bp & 0xffffu), bS = (int)(bp >> 16);
    int p = atomicAdd(&g_qcnt[bP], 1);
    if (p < CAPQ) g_qlistP[bP * CAPQ + p] = i;
    int s = atomicAdd(&g_qcnt[NB + bS], 1);
    if (s < CAPQ) g_qlistS[bS * CAPQ + s] = i;
}

// ---------------------------------------------------------------------------
// K1: R4-proven proj36 shape (256 blocks x 128 thr x 32 rows) + per-bin
// partial maxes over this slice's 32 keys for ALL 128 bins (thread t = bin t,
// LDS-broadcast reads, rides in the DRAM shadow) + per-slice |k|^2 max +
// per-bin query-list push.
// ---------------------------------------------------------------------------
__global__ __launch_bounds__(K1TH) void proj_part_kernel(
        const float* __restrict__ emb,
        const float* __restrict__ wqp, const float* __restrict__ wkp,
        const float* __restrict__ wvop, const float* __restrict__ wvarg,
        const float* __restrict__ wqs, const float* __restrict__ wks,
        const float* __restrict__ wvs) {
    __shared__ float sw[11 * PD];
    __shared__ float se[RPS * PD];
    __shared__ ulonglong2 sKxy[RPS];

    const int blk = blockIdx.x;          // slice id 0..NSL-1
    const int tid = threadIdx.x;
    const float DLT = TWO_PI_F / NB;
    const int base = blk * RPS;

    if (tid < 2 * PD) {
        sw[tid]          = wqp[tid];
        sw[2 * PD + tid] = wkp[tid];
        sw[4 * PD + tid] = wqs[tid];
        sw[6 * PD + tid] = wks[tid];
    }
    if (tid < PD) {
        sw[8 * PD + tid]  = wvop[tid];
        sw[9 * PD + tid]  = wvarg[tid];
        sw[10 * PD + tid] = wvs[tid];
    }
    {
        const float4* emb4 = (const float4*)(emb + (size_t)base * PD);
#pragma unroll
        for (int v = 0; v < (RPS * PD / 4 + K1TH - 1) / K1TH; v++) {
            int idx = tid + v * K1TH;
            if (idx < RPS * PD / 4) ((float4*)se)[idx] = emb4[idx];
        }
    }
    __syncthreads();

    {
        const int row = tid >> 2, part = tid & 3;
        const float* r0 = se + row * PD + part * 9;
        float rv[9];
#pragma unroll
        for (int dd = 0; dd < 9; dd++) rv[dd] = r0[dd];
        // c: 0=Qp.x 1=Qp.y 2=Kp.x 3=Kp.y 4=Qs.x 5=Qs.y 6=Ks.x 7=Ks.y 8=Vop 9=Varg 10=Vstk
        float a[11];
#pragma unroll
        for (int c = 0; c < 11; c++) a[c] = 0.f;
#pragma unroll
        for (int c = 0; c < 11; c++) {
            const float* wc = sw + c * PD + part * 9;
#pragma unroll
            for (int dd = 0; dd < 9; dd++) a[c] = fmaf(rv[dd], wc[dd], a[c]);
        }
#pragma unroll
        for (int c = 0; c < 11; c++) {
            a[c] += __shfl_down_sync(0xffffffffu, a[c], 1);
            a[c] += __shfl_down_sync(0xffffffffu, a[c], 2);
        }
        if (part == 0) {
            int i = base + row;
            ulonglong2 kk = make_ulonglong2(packf2(a[2], a[6]), packf2(a[3], a[7]));
            g_QQ[i] = make_ulonglong2(packf2(a[0], a[4]), packf2(a[1], a[5]));
            g_KK[i] = kk;
            sKxy[row] = kk;
            unsigned bp = qbins(a[0], a[1], a[4], a[5]);
            g_binPS[i] = bp;
            g_Vop[i] = a[8]; g_Varg[i] = a[9]; g_Vstk[i] = a[10];
            push_query(i, bp);
        }
    }
    __syncthreads();

    // partials: thread tid == bin tid (exactly 128 bins). Keys broadcast
    // from smem; same fma2/cosf bit patterns K2 re-derives.
    {
        const float thc = -PI_F + (tid + 0.5f) * DLT;
        const float ux = cosf(thc), uy = sinf(thc);
        const unsigned long long ua = packf2(ux, ux), ub = packf2(uy, uy);
        float mP = -FLT_MAX, mS = -FLT_MAX;
#pragma unroll 4
        for (int k = 0; k < RPS; k++) {
            ulonglong2 kk = sKxy[k];
            unsigned long long s = fma2(ua, kk.x, mul2(ub, kk.y));
            mP = fmaxf(mP, lo32(s));
            mS = fmaxf(mS, hi32(s));
        }
        g_sPartP[tid * NSL + blk] = mP;
        g_sPartS[tid * NSL + blk] = mS;
    }
    // per-slice |k|^2 max (warp 0)
    if (tid < RPS) {
        ulonglong2 kk = sKxy[tid];
        unsigned long long n2 = fma2(kk.x, kk.x, mul2(kk.y, kk.y));
        float np = lo32(n2), ns = hi32(n2);
#pragma unroll
        for (int off = 16; off; off >>= 1) {
            np = fmaxf(np, __shfl_xor_sync(0xffffffffu, np, off));
            ns = fmaxf(ns, __shfl_xor_sync(0xffffffffu, ns, off));
        }
        if (tid == 0) { g_n2P[blk] = np; g_n2S[blk] = ns; }
    }
}

// ---------------------------------------------------------------------------
// K2: one block per bin, 512 threads, 3 dependent memory rounds.
//  R1: load ALL independent data at once (partials, n2, qlists, qcnt).
//  ALU: reduce -> exact threshold M - 1.25*Kmax*DLT (max-of-maxes ==
//       full-scan max; proven construction) -> hot-slice select (slice hot
//       IFF partial >= thresh; identical fp inputs => lossless).
//  R2: load hot-slice keys + their V + this bin's query QQ (parallel).
//  R3 (smem-only): candidate filter (scalar fmaf/fmul_rn == f32x2 lanes),
//       resolve with exact scores + first-index tie-break, store out.
//  Fallbacks (never expected): hot/cand overflow or qlist overflow -> exact
//  brute resolve for this bin's queries via g_binPS scan.
// ---------------------------------------------------------------------------
__global__ __launch_bounds__(K2TH) void bin_query_kernel(float* __restrict__ out, int T) {
    __shared__ float sPartP[NSL], sPartS[NSL];
    __shared__ int sqlP[CAPQ], sqlS[CAPQ];
    __shared__ float2 sQP[CAPQ], sQS[CAPQ];
    __shared__ float2 sHKP[HOTMAX * RPS], sHKS[HOTMAX * RPS];
    __shared__ float sHVop[HOTMAX * RPS], sHVarg[HOTMAX * RPS], sHVstk[HOTMAX * RPS];
    __shared__ int sHotP[HOTMAX], sHotS[HOTMAX];
    __shared__ int sNhot[2];
    __shared__ int scIdx[2][CAP], scOff[2][CAP];
    __shared__ int scnt[2];
    __shared__ float sredM[16], sredN[16];
    __shared__ float sth[2];

    const int b = blockIdx.x;
    const int tid = threadIdx.x, lane = tid & 31, w = tid >> 5;
    const float DLT = TWO_PI_F / NB;
    const float thb = -PI_F + (b + 0.5f) * DLT;
    const float ux = cosf(thb), uy = sinf(thb);   // bit-identical to K1's bin b

    if (tid < 2) { scnt[tid] = 0; sNhot[tid] = 0; }

    // ===== Round 1: all independent loads =====
    const int totP = __ldcg(&g_qcnt[b]);
    const int totS = __ldcg(&g_qcnt[NB + b]);
    const int nqP = min(totP, CAPQ), nqS = min(totS, CAPQ);

    float myPart = -FLT_MAX, myN2 = 0.f;   // per-thread: t<256 -> P slice t; t>=256 -> S slice t-256
    if (tid < NSL) {
        myPart = __ldcg(&g_sPartP[b * NSL + tid]);
        myN2   = __ldcg(&g_n2P[tid]);
        sPartP[tid] = myPart;
    } else {
        myPart = __ldcg(&g_sPartS[b * NSL + (tid - NSL)]);
        myN2   = __ldcg(&g_n2S[tid - NSL]);
        sPartS[tid - NSL] = myPart;
    }
    // qlists: load full CAPQ unconditionally (stale entries unused; safe)
    for (int t = tid; t < CAPQ; t += K2TH) {
        sqlP[t] = __ldcg(&g_qlistP[b * CAPQ + t]);
        sqlS[t] = __ldcg(&g_qlistS[b * CAPQ + t]);
    }

    // reduce M and Kmax^2 per head (warps 0-7: P, warps 8-15: S)
    {
        float m = myPart, n = myN2;
#pragma unroll
        for (int off = 16; off; off >>= 1) {
            m = fmaxf(m, __shfl_xor_sync(0xffffffffu, m, off));
            n = fmaxf(n, __shfl_xor_sync(0xffffffffu, n, off));
        }
        if (lane == 0) { sredM[w] = m; sredN[w] = n; }
    }
    __syncthreads();
    if (tid == 0) {
        float MP = sredM[0], NP = sredN[0], MS = sredM[8], NS = sredN[8];
#pragma unroll
        for (int k = 1; k < 8; k++) {
            MP = fmaxf(MP, sredM[k]);     NP = fmaxf(NP, sredN[k]);
            MS = fmaxf(MS, sredM[8 + k]); NS = fmaxf(NS, sredN[8 + k]);
        }
        // Exact-cover threshold (proven R4/6/7/8/11/12): argmax key of any
        // direction in this bin has s_u >= M - Kmax*DLT; 1.25 absorbs fp slop.
        sth[0] = MP - 1.25f * sqrtf(NP) * DLT;
        sth[1] = MS - 1.25f * sqrtf(NS) * DLT;
    }
    __syncthreads();
    const float tP = sth[0], tS = sth[1];

    // hot-slice select: slice g hot IFF partial[b,g] >= thresh (lossless)
    if (tid < NSL) {
        if (sPartP[tid] >= tP) { int p = atomicAdd(&sNhot[0], 1); if (p < HOTMAX) sHotP[p] = tid; }
    } else {
        if (sPartS[tid - NSL] >= tS) { int p = atomicAdd(&sNhot[1], 1); if (p < HOTMAX) sHotS[p] = tid - NSL; }
    }
    __syncthreads();
    const int nbP = sNhot[0], nbS = sNhot[1];
    const int nbP2 = min(nbP, HOTMAX), nbS2 = min(nbS, HOTMAX);

    // ===== Round 2: hot keys + V + query QQ (all parallel) =====
    for (int idx = tid; idx < nbP2 * RPS; idx += K2TH) {
        const int j = sHotP[idx >> 5] * RPS + (idx & (RPS - 1));
        ulonglong2 kk = ldcg_u2(&g_KK[j]);
        sHKP[idx] = make_float2(lo32(kk.x), lo32(kk.y));
        sHVop[idx] = __ldcg(&g_Vop[j]);
        sHVarg[idx] = __ldcg(&g_Varg[j]);
    }
    for (int idx = tid; idx < nbS2 * RPS; idx += K2TH) {
        const int j = sHotS[idx >> 5] * RPS + (idx & (RPS - 1));
        ulonglong2 kk = ldcg_u2(&g_KK[j]);
        sHKS[idx] = make_float2(hi32(kk.x), hi32(kk.y));
        sHVstk[idx] = __ldcg(&g_Vstk[j]);
    }
    for (int t = tid; t < nqP; t += K2TH) {
        ulonglong2 q = ldcg_u2(&g_QQ[sqlP[t]]);
        sQP[t] = make_float2(lo32(q.x), lo32(q.y));
    }
    for (int t = tid; t < nqS; t += K2TH) {
        ulonglong2 q = ldcg_u2(&g_QQ[sqlS[t]]);
        sQS[t] = make_float2(hi32(q.x), hi32(q.y));
    }
    __syncthreads();

    // ===== Round 3 (smem-only): filter + resolve =====
    for (int idx = tid; idx < nbP2 * RPS; idx += K2TH) {
        float2 k = sHKP[idx];
        float s = fmaf(ux, k.x, __fmul_rn(uy, k.y));   // == f32x2 lo lane
        if (s >= tP) {
            int p = atomicAdd(&scnt[0], 1);
            if (p < CAP) {
                scIdx[0][p] = sHotP[idx >> 5] * RPS + (idx & (RPS - 1));
                scOff[0][p] = idx;
            }
        }
    }
    for (int idx = tid; idx < nbS2 * RPS; idx += K2TH) {
        float2 k = sHKS[idx];
        float s = fmaf(ux, k.x, __fmul_rn(uy, k.y));   // == f32x2 hi lane
        if (s >= tS) {
            int p = atomicAdd(&scnt[1], 1);
            if (p < CAP) {
                scIdx[1][p] = sHotS[idx >> 5] * RPS + (idx & (RPS - 1));
                scOff[1][p] = idx;
            }
        }
    }
    __syncthreads();
    const int nP = min(scnt[0], CAP), nS = min(scnt[1], CAP);
    const bool okP = (nbP <= HOTMAX) && (scnt[0] <= CAP) && (totP <= CAPQ);
    const bool okS = (nbS <= HOTMAX) && (scnt[1] <= CAP) && (totS <= CAPQ);

    if (okP) {
        for (int t = tid; t < nqP; t += K2TH) {
            const float qx = sQP[t].x, qy = sQP[t].y;
            float best = -FLT_MAX; int bi = 0x7fffffff, bo = 0;
            for (int c = 0; c < nP; c++) {
                int kj = scIdx[0][c];
                float2 k = sHKP[scOff[0][c]];
                float sc = fmaf(qx, k.x, __fmul_rn(qy, k.y));
                if (sc > best || (sc == best && kj < bi)) { best = sc; bi = kj; bo = scOff[0][c]; }
            }
            const int i = sqlP[t];
            out[i]     = sHVop[bo];
            out[T + i] = sHVarg[bo];
        }
    } else {
        // exact brute fallback for every query of this bin (never expected)
        for (int j = tid; j < T; j += K2TH) {
            if ((__ldcg(&g_binPS[j]) & 0xffffu) == (unsigned)b) {
                ulonglong2 q = ldcg_u2(&g_QQ[j]);
                const float qx = lo32(q.x), qy = lo32(q.y);
                float best = -FLT_MAX; int bi = 0;
                for (int kjj = 0; kjj < T; kjj++) {
                    ulonglong2 k2 = ldcg_u2(&g_KK[kjj]);
                    float sc = fmaf(qx, lo32(k2.x), __fmul_rn(qy, lo32(k2.y)));
                    if (sc > best) { best = sc; bi = kjj; }
                }
                out[j]     = __ldcg(&g_Vop[bi]);
                out[T + j] = __ldcg(&g_Varg[bi]);
            }
        }
    }
    if (okS) {
        for (int t = tid; t < nqS; t += K2TH) {
            const float qx = sQS[t].x, qy = sQS[t].y;
            float best = -FLT_MAX; int bi = 0x7fffffff, bo = 0;
            for (int c = 0; c < nS; c++) {
                int kj = scIdx[1][c];
                float2 k = sHKS[scOff[1][c]];
                float sc = fmaf(qx, k.x, __fmul_rn(qy, k.y));
                if (sc > best || (sc == best && kj < bi)) { best = sc; bi = kj; bo = scOff[1][c]; }
            }
            out[2 * T + sqlS[t]] = sHVstk[bo];
        }
    } else {
        for (int j = tid; j < T; j += K2TH) {
            if ((__ldcg(&g_binPS[j]) >> 16) == (unsigned)b) {
                ulonglong2 q = ldcg_u2(&g_QQ[j]);
                const float qx = hi32(q.x), qy = hi32(q.y);
                float best = -FLT_MAX; int bi = 0;
                for (int kjj = 0; kjj < T; kjj++) {
                    ulonglong2 k2 = ldcg_u2(&g_KK[kjj]);
                    float sc = fmaf(qx, hi32(k2.x), __fmul_rn(qy, hi32(k2.y)));
                    if (sc > best) { best = sc; bi = kjj; }
                }
                out[2 * T + j] = __ldcg(&g_Vstk[bi]);
            }
        }
    }

    __syncthreads();
    if (tid == 0) { g_qcnt[b] = 0; g_qcnt[NB + b] = 0; }   // self-reset
}

// ---------------------------------------------------------------------------
// Generic fallback (D != 36 or T != MAXT): projection + brute-force argmax.
// ---------------------------------------------------------------------------
__global__ void proj_generic_kernel(
        const float* __restrict__ emb,
        const float* __restrict__ wqp, const float* __restrict__ wkp,
        const float* __restrict__ wvop, const float* __restrict__ wvarg,
        const float* __restrict__ wqs, const float* __restrict__ wks,
        const float* __restrict__ wvs, int T, int D) {
    extern __shared__ float sw[];
    const int tid = threadIdx.x;
    for (int k = tid; k < 2 * D; k += blockDim.x) {
        sw[k]         = wqp[k];
        sw[2 * D + k] = wkp[k];
        sw[4 * D + k] = wqs[k];
        sw[6 * D + k] = wks[k];
    }
    for (int k = tid; k < D; k += blockDim.x) {
        sw[8 * D + k]  = wvop[k];
        sw[9 * D + k]  = wvarg[k];
        sw[10 * D + k] = wvs[k];
    }
    __syncthreads();
    int i = blockIdx.x * blockDim.x + tid;
    if (i >= T) return;
    const float* e = emb + (size_t)i * D;
    float a[11];
#pragma unroll
    for (int c = 0; c < 11; c++) a[c] = 0.f;
    for (int d = 0; d < D; d++) {
        float ev = e[d];
#pragma unroll
        for (int c = 0; c < 11; c++) a[c] = fmaf(ev, sw[c * D + d], a[c]);
    }
    g_QQ[i] = make_ulonglong2(packf2(a[0], a[4]), packf2(a[1], a[5]));
    g_KK[i] = make_ulonglong2(packf2(a[2], a[6]), packf2(a[3], a[7]));
    g_Vop[i] = a[8]; g_Varg[i] = a[9]; g_Vstk[i] = a[10];
}

__global__ void brute_generic_kernel(float* __restrict__ out, int T) {
    const int gidx = blockIdx.x * blockDim.x + threadIdx.x;
    const int i = gidx >> 1, head = gidx & 1;
    if (i >= T) return;
    ulonglong2 q = g_QQ[i];
    const float qx = head ? hi32(q.x) : lo32(q.x);
    const float qy = head ? hi32(q.y) : lo32(q.y);
    float best = -FLT_MAX; int bi = 0;
    for (int j = 0; j < T; j++) {
        ulonglong2 k2 = g_KK[j];
        float kx = head ? hi32(k2.x) : lo32(k2.x);
        float ky = head ? hi32(k2.y) : lo32(k2.y);
        float sc = fmaf(qx, kx, __fmul_rn(qy, ky));
        if (sc > best) { best = sc; bi = j; }
    }
    if (head == 0) {
        out[i]     = g_Vop[bi];
        out[T + i] = g_Varg[bi];
    } else {
        out[2 * T + i] = g_Vstk[bi];
    }
}

extern "C" void kernel_launch(void* const* d_in, const int* in_sizes, int n_in,
                              void* d_out, int out_size) {
    const float* emb   = (const float*)d_in[0];
    const float* wqp   = (const float*)d_in[1];
    const float* wkp   = (const float*)d_in[2];
    const float* wvop  = (const float*)d_in[3];
    const float* wvarg = (const float*)d_in[4];
    const float* wqs   = (const float*)d_in[5];
    const float* wks   = (const float*)d_in[6];
    const float* wvs   = (const float*)d_in[7];
    float* out = (float*)d_out;

    const int D = in_sizes[1] / 2;   // WQ_prog is (2, D)
    const int T = in_sizes[0] / D;   // embeddings is (T, D)

    if (D == PD && T == MAXT) {
        proj_part_kernel<<<NSL, K1TH>>>(emb, wqp, wkp, wvop, wvarg, wqs, wks, wvs);
        bin_query_kernel<<<NB, K2TH>>>(out, T);
    } else {
        const int pb = (T + 255) / 256;
        proj_generic_kernel<<<pb, 256, (size_t)(11 * D) * sizeof(float)>>>(
            emb, wqp, wkp, wvop, wvarg, wqs, wks, wvs, T, D);
        brute_generic_kernel<<<(2 * T + 255) / 256, 256>>>(out, T);
    }
}

// round 15
// speedup vs baseline: 4.2848x; 4.2848x over previous
#include <cuda_runtime.h>
#include <float.h>
#include <math.h>

#define MAXT 8192
#define NB   128          // direction bins (K2 grid)
#define NSL  256          // key slices (K1 grid), 32 rows each
#define RPS  32           // rows per slice
#define CAP  128          // max key candidates per bin (expect ~2-10)
#define CAPQ 768          // max queries per bin list (R12/R13-proven sufficient)
#define HOTMAX 16         // max hot slices cached in smem (expect 1-4; fallback)
#define PD   36
#define K1TH 128
#define K2TH 512

// Device scratch (graph-capturable: no allocs). g_qcnt self-resets (K2
// zeroes its own bins at the end; zero-initialized at load). All other
// arrays are fully rewritten by K1 each launch before K2 reads them.
// Stale qlist entries beyond qcnt are never used (loads of them are safe).
__device__ ulonglong2 g_QQ[MAXT], g_KK[MAXT];
__device__ unsigned g_binPS[MAXT];
__device__ float g_Vop[MAXT], g_Varg[MAXT], g_Vstk[MAXT];
__device__ float g_sPartP[NB * NSL], g_sPartS[NB * NSL];  // [bin*NSL + slice]
__device__ float g_n2P[NSL], g_n2S[NSL];                  // per-slice |k|^2 max
__device__ int g_qcnt[2 * NB];
__device__ int g_qlistP[NB * CAPQ], g_qlistS[NB * CAPQ];

__device__ __forceinline__ unsigned long long packf2(float lo, float hi) {
    return ((unsigned long long)__float_as_uint(hi) << 32) | (unsigned long long)__float_as_uint(lo);
}
__device__ __forceinline__ float lo32(unsigned long long v) { return __uint_as_float((unsigned)v); }
__device__ __forceinline__ float hi32(unsigned long long v) { return __uint_as_float((unsigned)(v >> 32)); }

// sm_103a packed fp32 pair math (PTX-only; per-lane rounding == scalar rn).
__device__ __forceinline__ unsigned long long mul2(unsigned long long a, unsigned long long b) {
    unsigned long long r;
    asm("mul.rn.f32x2 %0, %1, %2;" : "=l"(r) : "l"(a), "l"(b));
    return r;
}
__device__ __forceinline__ unsigned long long fma2(unsigned long long a, unsigned long long b, unsigned long long c) {
    unsigned long long r;
    asm("fma.rn.f32x2 %0, %1, %2, %3;" : "=l"(r) : "l"(a), "l"(b), "l"(c));
    return r;
}

__device__ __forceinline__ ulonglong2 ldcg_u2(const ulonglong2* p) {
    uint4 v = __ldcg((const uint4*)p);
    ulonglong2 r;
    r.x = ((unsigned long long)v.y << 32) | v.x;
    r.y = ((unsigned long long)v.w << 32) | v.z;
    return r;
}

#define PI_F 3.14159265358979f
#define TWO_PI_F 6.2831853071795865f

__device__ __forceinline__ unsigned qbins(float qpx, float qpy, float qsx, float qsy) {
    const float SC = NB / TWO_PI_F;
    int bP = (int)((atan2f(qpy, qpx) + PI_F) * SC);
    bP = min(max(bP, 0), NB - 1);
    int bS = (int)((atan2f(qsy, qsx) + PI_F) * SC);
    bS = min(max(bS, 0), NB - 1);
    return (unsigned)bP | ((unsigned)bS << 16);
}

__device__ __forceinline__ void push_query(int i, unsigned bp) {
    const int bP = (int)(bp & 0xffffu), bS = (int)(bp >> 16);
    int p = atomicAdd(&g_qcnt[bP], 1);
    if (p < CAPQ) g_qlistP[bP * CAPQ + p] = i;
    int s = atomicAdd(&g_qcnt[NB + bS], 1);
    if (s < CAPQ) g_qlistS[bS * CAPQ + s] = i;
}

// Exact brute argmax for one query/head over all keys, MLP-8 batched.
// Used only by the (never-expected) fallback paths.
__device__ void brute_one(float qx, float qy, int head, int i, float* out, int T) {
    float best = -FLT_MAX; int bi = 0;
    for (int j0 = 0; j0 < T; j0 += 8) {
        ulonglong2 kb[8];
#pragma unroll
        for (int u = 0; u < 8; u++) kb[u] = ldcg_u2(&g_KK[j0 + u]);
#pragma unroll
        for (int u = 0; u < 8; u++) {
            float kx = head ? hi32(kb[u].x) : lo32(kb[u].x);
            float ky = head ? hi32(kb[u].y) : lo32(kb[u].y);
            float sc = fmaf(qx, kx, __fmul_rn(qy, ky));
            if (sc > best) { best = sc; bi = j0 + u; }
        }
    }
    if (head == 0) {
        out[i]     = __ldcg(&g_Vop[bi]);
        out[T + i] = __ldcg(&g_Varg[bi]);
    } else {
        out[2 * T + i] = __ldcg(&g_Vstk[bi]);
    }
}

// ---------------------------------------------------------------------------
// K1: R4-proven proj36 shape (256 blocks x 128 thr x 32 rows) + per-bin
// partial maxes over this slice's 32 keys for ALL 128 bins (thread t = bin t,
// LDS-broadcast reads, rides in the DRAM shadow) + per-slice |k|^2 max +
// per-bin query-list push.
// ---------------------------------------------------------------------------
__global__ __launch_bounds__(K1TH) void proj_part_kernel(
        const float* __restrict__ emb,
        const float* __restrict__ wqp, const float* __restrict__ wkp,
        const float* __restrict__ wvop, const float* __restrict__ wvarg,
        const float* __restrict__ wqs, const float* __restrict__ wks,
        const float* __restrict__ wvs) {
    __shared__ float sw[11 * PD];
    __shared__ float se[RPS * PD];
    __shared__ ulonglong2 sKxy[RPS];

    const int blk = blockIdx.x;          // slice id 0..NSL-1
    const int tid = threadIdx.x;
    const float DLT = TWO_PI_F / NB;
    const int base = blk * RPS;

    if (tid < 2 * PD) {
        sw[tid]          = wqp[tid];
        sw[2 * PD + tid] = wkp[tid];
        sw[4 * PD + tid] = wqs[tid];
        sw[6 * PD + tid] = wks[tid];
    }
    if (tid < PD) {
        sw[8 * PD + tid]  = wvop[tid];
        sw[9 * PD + tid]  = wvarg[tid];
        sw[10 * PD + tid] = wvs[tid];
    }
    {
        const float4* emb4 = (const float4*)(emb + (size_t)base * PD);
#pragma unroll
        for (int v = 0; v < (RPS * PD / 4 + K1TH - 1) / K1TH; v++) {
            int idx = tid + v * K1TH;
            if (idx < RPS * PD / 4) ((float4*)se)[idx] = emb4[idx];
        }
    }
    __syncthreads();

    {
        const int row = tid >> 2, part = tid & 3;
        const float* r0 = se + row * PD + part * 9;
        float rv[9];
#pragma unroll
        for (int dd = 0; dd < 9; dd++) rv[dd] = r0[dd];
        // c: 0=Qp.x 1=Qp.y 2=Kp.x 3=Kp.y 4=Qs.x 5=Qs.y 6=Ks.x 7=Ks.y 8=Vop 9=Varg 10=Vstk
        float a[11];
#pragma unroll
        for (int c = 0; c < 11; c++) a[c] = 0.f;
#pragma unroll
        for (int c = 0; c < 11; c++) {
            const float* wc = sw + c * PD + part * 9;
#pragma unroll
            for (int dd = 0; dd < 9; dd++) a[c] = fmaf(rv[dd], wc[dd], a[c]);
        }
#pragma unroll
        for (int c = 0; c < 11; c++) {
            a[c] += __shfl_down_sync(0xffffffffu, a[c], 1);
            a[c] += __shfl_down_sync(0xffffffffu, a[c], 2);
        }
        if (part == 0) {
            int i = base + row;
            ulonglong2 kk = make_ulonglong2(packf2(a[2], a[6]), packf2(a[3], a[7]));
            g_QQ[i] = make_ulonglong2(packf2(a[0], a[4]), packf2(a[1], a[5]));
            g_KK[i] = kk;
            sKxy[row] = kk;
            unsigned bp = qbins(a[0], a[1], a[4], a[5]);
            g_binPS[i] = bp;
            g_Vop[i] = a[8]; g_Varg[i] = a[9]; g_Vstk[i] = a[10];
            push_query(i, bp);
        }
    }
    __syncthreads();

    // partials: thread tid == bin tid (exactly 128 bins). Keys broadcast
    // from smem; same fma2/cosf bit patterns K2 re-derives.
    {
        const float thc = -PI_F + (tid + 0.5f) * DLT;
        const float ux = cosf(thc), uy = sinf(thc);
        const unsigned long long ua = packf2(ux, ux), ub = packf2(uy, uy);
        float mP = -FLT_MAX, mS = -FLT_MAX;
#pragma unroll 4
        for (int k = 0; k < RPS; k++) {
            ulonglong2 kk = sKxy[k];
            unsigned long long s = fma2(ua, kk.x, mul2(ub, kk.y));
            mP = fmaxf(mP, lo32(s));
            mS = fmaxf(mS, hi32(s));
        }
        g_sPartP[tid * NSL + blk] = mP;
        g_sPartS[tid * NSL + blk] = mS;
    }
    // per-slice |k|^2 max (warp 0)
    if (tid < RPS) {
        ulonglong2 kk = sKxy[tid];
        unsigned long long n2 = fma2(kk.x, kk.x, mul2(kk.y, kk.y));
        float np = lo32(n2), ns = hi32(n2);
#pragma unroll
        for (int off = 16; off; off >>= 1) {
            np = fmaxf(np, __shfl_xor_sync(0xffffffffu, np, off));
            ns = fmaxf(ns, __shfl_xor_sync(0xffffffffu, ns, off));
        }
        if (tid == 0) { g_n2P[blk] = np; g_n2S[blk] = ns; }
    }
}

// ---------------------------------------------------------------------------
// K2: one block per bin, 512 threads, 3 dependent memory rounds (measured
// 1.3us in R14).
//  R1: load ALL independent data at once (partials, n2, qlists, qcnt).
//  ALU: reduce -> exact threshold M - 1.25*Kmax*DLT (max-of-maxes ==
//       full-scan max; proven construction) -> hot-slice select (slice hot
//       IFF partial >= thresh; identical fp inputs => lossless).
//  R2: load hot-slice keys + their V + this bin's query QQ (parallel).
//  R3 (smem-only): candidate filter (scalar fmaf/fmul_rn == f32x2 lanes),
//       resolve with exact scores + first-index tie-break, store out.
//  Fallbacks (never expected, MLP-8 batched so non-catastrophic).
// ---------------------------------------------------------------------------
__global__ __launch_bounds__(K2TH) void bin_query_kernel(float* __restrict__ out, int T) {
    __shared__ float sPartP[NSL], sPartS[NSL];
    __shared__ int sqlP[CAPQ], sqlS[CAPQ];
    __shared__ float2 sQP[CAPQ], sQS[CAPQ];
    __shared__ float2 sHKP[HOTMAX * RPS], sHKS[HOTMAX * RPS];
    __shared__ float sHVop[HOTMAX * RPS], sHVarg[HOTMAX * RPS], sHVstk[HOTMAX * RPS];
    __shared__ int sHotP[HOTMAX], sHotS[HOTMAX];
    __shared__ int sNhot[2];
    __shared__ int scIdx[2][CAP], scOff[2][CAP];
    __shared__ int scnt[2];
    __shared__ float sredM[16], sredN[16];
    __shared__ float sth[2];

    const int b = blockIdx.x;
    const int tid = threadIdx.x, lane = tid & 31, w = tid >> 5;
    const float DLT = TWO_PI_F / NB;
    const float thb = -PI_F + (b + 0.5f) * DLT;
    const float ux = cosf(thb), uy = sinf(thb);   // bit-identical to K1's bin b

    if (tid < 2) { scnt[tid] = 0; sNhot[tid] = 0; }

    // ===== Round 1: all independent loads =====
    const int totP = __ldcg(&g_qcnt[b]);
    const int totS = __ldcg(&g_qcnt[NB + b]);
    const int nqP = min(totP, CAPQ), nqS = min(totS, CAPQ);

    float myPart, myN2;   // t<256 -> P slice t; t>=256 -> S slice t-256
    if (tid < NSL) {
        myPart = __ldcg(&g_sPartP[b * NSL + tid]);
        myN2   = __ldcg(&g_n2P[tid]);
        sPartP[tid] = myPart;
    } else {
        myPart = __ldcg(&g_sPartS[b * NSL + (tid - NSL)]);
        myN2   = __ldcg(&g_n2S[tid - NSL]);
        sPartS[tid - NSL] = myPart;
    }
    // qlists: load only live entries (stale entries unused)
    for (int t = tid; t < nqP; t += K2TH) sqlP[t] = __ldcg(&g_qlistP[b * CAPQ + t]);
    for (int t = tid; t < nqS; t += K2TH) sqlS[t] = __ldcg(&g_qlistS[b * CAPQ + t]);

    // reduce M and Kmax^2 per head (warps 0-7: P, warps 8-15: S)
    {
        float m = myPart, n = myN2;
#pragma unroll
        for (int off = 16; off; off >>= 1) {
            m = fmaxf(m, __shfl_xor_sync(0xffffffffu, m, off));
            n = fmaxf(n, __shfl_xor_sync(0xffffffffu, n, off));
        }
        if (lane == 0) { sredM[w] = m; sredN[w] = n; }
    }
    __syncthreads();
    if (tid == 0) {
        float MP = sredM[0], NP = sredN[0], MS = sredM[8], NS = sredN[8];
#pragma unroll
        for (int k = 1; k < 8; k++) {
            MP = fmaxf(MP, sredM[k]);     NP = fmaxf(NP, sredN[k]);
            MS = fmaxf(MS, sredM[8 + k]); NS = fmaxf(NS, sredN[8 + k]);
        }
        // Exact-cover threshold (proven R4/6/7/8/11/12): argmax key of any
        // direction in this bin has s_u >= M - Kmax*DLT; 1.25 absorbs fp slop.
        sth[0] = MP - 1.25f * sqrtf(NP) * DLT;
        sth[1] = MS - 1.25f * sqrtf(NS) * DLT;
    }
    __syncthreads();
    const float tP = sth[0], tS = sth[1];

    // hot-slice select: slice g hot IFF partial[b,g] >= thresh (lossless)
    if (tid < NSL) {
        if (sPartP[tid] >= tP) { int p = atomicAdd(&sNhot[0], 1); if (p < HOTMAX) sHotP[p] = tid; }
    } else {
        if (sPartS[tid - NSL] >= tS) { int p = atomicAdd(&sNhot[1], 1); if (p < HOTMAX) sHotS[p] = tid - NSL; }
    }
    __syncthreads();
    const int nbP = sNhot[0], nbS = sNhot[1];
    const int nbP2 = min(nbP, HOTMAX), nbS2 = min(nbS, HOTMAX);

    // ===== Round 2: hot keys + V + query QQ (all parallel) =====
    for (int idx = tid; idx < nbP2 * RPS; idx += K2TH) {
        const int j = sHotP[idx >> 5] * RPS + (idx & (RPS - 1));
        ulonglong2 kk = ldcg_u2(&g_KK[j]);
        sHKP[idx] = make_float2(lo32(kk.x), lo32(kk.y));
        sHVop[idx] = __ldcg(&g_Vop[j]);
        sHVarg[idx] = __ldcg(&g_Varg[j]);
    }
    for (int idx = tid; idx < nbS2 * RPS; idx += K2TH) {
        const int j = sHotS[idx >> 5] * RPS + (idx & (RPS - 1));
        ulonglong2 kk = ldcg_u2(&g_KK[j]);
        sHKS[idx] = make_float2(hi32(kk.x), hi32(kk.y));
        sHVstk[idx] = __ldcg(&g_Vstk[j]);
    }
    for (int t = tid; t < nqP; t += K2TH) {
        ulonglong2 q = ldcg_u2(&g_QQ[sqlP[t]]);
        sQP[t] = make_float2(lo32(q.x), lo32(q.y));
    }
    for (int t = tid; t < nqS; t += K2TH) {
        ulonglong2 q = ldcg_u2(&g_QQ[sqlS[t]]);
        sQS[t] = make_float2(hi32(q.x), hi32(q.y));
    }
    __syncthreads();

    // ===== Round 3 (smem-only): filter + resolve =====
    for (int idx = tid; idx < nbP2 * RPS; idx += K2TH) {
        float2 k = sHKP[idx];
        float s = fmaf(ux, k.x, __fmul_rn(uy, k.y));   // == f32x2 lo lane
        if (s >= tP) {
            int p = atomicAdd(&scnt[0], 1);
            if (p < CAP) {
                scIdx[0][p] = sHotP[idx >> 5] * RPS + (idx & (RPS - 1));
                scOff[0][p] = idx;
            }
        }
    }
    for (int idx = tid; idx < nbS2 * RPS; idx += K2TH) {
        float2 k = sHKS[idx];
        float s = fmaf(ux, k.x, __fmul_rn(uy, k.y));   // == f32x2 hi lane
        if (s >= tS) {
            int p = atomicAdd(&scnt[1], 1);
            if (p < CAP) {
                scIdx[1][p] = sHotS[idx >> 5] * RPS + (idx & (RPS - 1));
                scOff[1][p] = idx;
            }
        }
    }
    __syncthreads();
    const int nP = min(scnt[0], CAP), nS = min(scnt[1], CAP);
    const bool okP = (nbP <= HOTMAX) && (scnt[0] <= CAP) && (totP <= CAPQ);
    const bool okS = (nbS <= HOTMAX) && (scnt[1] <= CAP) && (totS <= CAPQ);

    if (okP) {
        for (int t = tid; t < nqP; t += K2TH) {
            const float qx = sQP[t].x, qy = sQP[t].y;
            float best = -FLT_MAX; int bi = 0x7fffffff, bo = 0;
            for (int c = 0; c < nP; c++) {
                int kj = scIdx[0][c];
                float2 k = sHKP[scOff[0][c]];
                float sc = fmaf(qx, k.x, __fmul_rn(qy, k.y));
                if (sc > best || (sc == best && kj < bi)) { best = sc; bi = kj; bo = scOff[0][c]; }
            }
            const int i = sqlP[t];
            out[i]     = sHVop[bo];
            out[T + i] = sHVarg[bo];
        }
    } else if (totP <= CAPQ) {
        // exact brute per owned query (never expected), MLP-8 batched
        for (int t = tid; t < nqP; t += K2TH) {
            const int i = sqlP[t];
            ulonglong2 q = ldcg_u2(&g_QQ[i]);
            brute_one(lo32(q.x), lo32(q.y), 0, i, out, T);
        }
    } else {
        for (int j = tid; j < T; j += K2TH) {
            if ((__ldcg(&g_binPS[j]) & 0xffffu) == (unsigned)b) {
                ulonglong2 q = ldcg_u2(&g_QQ[j]);
                brute_one(lo32(q.x), lo32(q.y), 0, j, out, T);
            }
        }
    }
    if (okS) {
        for (int t = tid; t < nqS; t += K2TH) {
            const float qx = sQS[t].x, qy = sQS[t].y;
            float best = -FLT_MAX; int bi = 0x7fffffff, bo = 0;
            for (int c = 0; c < nS; c++) {
                int kj = scIdx[1][c];
                float2 k = sHKS[scOff[1][c]];
                float sc = fmaf(qx, k.x, __fmul_rn(qy, k.y));
                if (sc > best || (sc == best && kj < bi)) { best = sc; bi = kj; bo = scOff[1][c]; }
            }
            out[2 * T + sqlS[t]] = sHVstk[bo];
        }
    } else if (totS <= CAPQ) {
        for (int t = tid; t < nqS; t += K2TH) {
            const int i = sqlS[t];
            ulonglong2 q = ldcg_u2(&g_QQ[i]);
            brute_one(hi32(q.x), hi32(q.y), 1, i, out, T);
        }
    } else {
        for (int j = tid; j < T; j += K2TH) {
            if ((__ldcg(&g_binPS[j]) >> 16) == (unsigned)b) {
                ulonglong2 q = ldcg_u2(&g_QQ[j]);
                brute_one(hi32(q.x), hi32(q.y), 1, j, out, T);
            }
        }
    }

    __syncthreads();
    if (tid == 0) { g_qcnt[b] = 0; g_qcnt[NB + b] = 0; }   // self-reset
}

// ---------------------------------------------------------------------------
// Generic fallback (D != 36 or T != MAXT): projection + brute-force argmax.
// ---------------------------------------------------------------------------
__global__ void proj_generic_kernel(
        const float* __restrict__ emb,
        const float* __restrict__ wqp, const float* __restrict__ wkp,
        const float* __restrict__ wvop, const float* __restrict__ wvarg,
        const float* __restrict__ wqs, const float* __restrict__ wks,
        const float* __restrict__ wvs, int T, int D) {
    extern __shared__ float sw[];
    const int tid = threadIdx.x;
    for (int k = tid; k < 2 * D; k += blockDim.x) {
        sw[k]         = wqp[k];
        sw[2 * D + k] = wkp[k];
        sw[4 * D + k] = wqs[k];
        sw[6 * D + k] = wks[k];
    }
    for (int k = tid; k < D; k += blockDim.x) {
        sw[8 * D + k]  = wvop[k];
        sw[9 * D + k]  = wvarg[k];
        sw[10 * D + k] = wvs[k];
    }
    __syncthreads();
    int i = blockIdx.x * blockDim.x + tid;
    if (i >= T) return;
    const float* e = emb + (size_t)i * D;
    float a[11];
#pragma unroll
    for (int c = 0; c < 11; c++) a[c] = 0.f;
    for (int d = 0; d < D; d++) {
        float ev = e[d];
#pragma unroll
        for (int c = 0; c < 11; c++) a[c] = fmaf(ev, sw[c * D + d], a[c]);
    }
    g_QQ[i] = make_ulonglong2(packf2(a[0], a[4]), packf2(a[1], a[5]));
    g_KK[i] = make_ulonglong2(packf2(a[2], a[6]), packf2(a[3], a[7]));
    g_Vop[i] = a[8]; g_Varg[i] = a[9]; g_Vstk[i] = a[10];
}

__global__ void brute_generic_kernel(float* __restrict__ out, int T) {
    const int gidx = blockIdx.x * blockDim.x + threadIdx.x;
    const int i = gidx >> 1, head = gidx & 1;
    if (i >= T) return;
    ulonglong2 q = g_QQ[i];
    const float qx = head ? hi32(q.x) : lo32(q.x);
    const float qy = head ? hi32(q.y) : lo32(q.y);
    float best = -FLT_MAX; int bi = 0;
    for (int j = 0; j < T; j++) {
        ulonglong2 k2 = g_KK[j];
        float kx = head ? hi32(k2.x) : lo32(k2.x);
        float ky = head ? hi32(k2.y) : lo32(k2.y);
        float sc = fmaf(qx, kx, __fmul_rn(qy, ky));
        if (sc > best) { best = sc; bi = j; }
    }
    if (head == 0) {
        out[i]     = g_Vop[bi];
        out[T + i] = g_Varg[bi];
    } else {
        out[2 * T + i] = g_Vstk[bi];
    }
}

extern "C" void kernel_launch(void* const* d_in, const int* in_sizes, int n_in,
                              void* d_out, int out_size) {
    const float* emb   = (const float*)d_in[0];
    const float* wqp   = (const float*)d_in[1];
    const float* wkp   = (const float*)d_in[2];
    const float* wvop  = (const float*)d_in[3];
    const float* wvarg = (const float*)d_in[4];
    const float* wqs   = (const float*)d_in[5];
    const float* wks   = (const float*)d_in[6];
    const float* wvs   = (const float*)d_in[7];
    float* out = (float*)d_out;

    const int D = in_sizes[1] / 2;   // WQ_prog is (2, D)
    const int T = in_sizes[0] / D;   // embeddings is (T, D)

    if (D == PD && T == MAXT) {
        proj_part_kernel<<<NSL, K1TH>>>(emb, wqp, wkp, wvop, wvarg, wqs, wks, wvs);
        bin_query_kernel<<<NB, K2TH>>>(out, T);
    } else {
        const int pb = (T + 255) / 256;
        proj_generic_kernel<<<pb, 256, (size_t)(11 * D) * sizeof(float)>>>(
            emb, wqp, wkp, wvop, wvarg, wqs, wks, wvs, T, D);
        brute_generic_kernel<<<(2 * T + 255) / 256, 256>>>(out, T);
    }
}

// round 16
// speedup vs baseline: 67.7665x; 15.8156x over previous
#include <cuda_runtime.h>
#include <float.h>
#include <math.h>

#define MAXT 8192
#define NB   128          // direction bins (K2 grid)
#define NSL  256          // key slices (K1 grid), 32 rows each
#define RPS  32           // rows per slice
#define CAP  128          // max key candidates per bin (expect ~2-10)
#define CAPQ 2048         // max queries per bin list (32x mean -- unreachable)
#define PD   36
#define K1TH 128
#define K2TH 512

// Device scratch (graph-capturable: no allocs). g_qcnt self-resets (K2
// zeroes its own bins at the end; zero-initialized at load). All other
// arrays are fully rewritten by K1 each launch before K2 reads them.
__device__ ulonglong2 g_QQ[MAXT], g_KK[MAXT];
__device__ unsigned g_binPS[MAXT];
__device__ float g_Vop[MAXT], g_Varg[MAXT], g_Vstk[MAXT];
__device__ float g_sPartP[NB * NSL], g_sPartS[NB * NSL];  // [bin*NSL + slice]
__device__ float g_n2P[NSL], g_n2S[NSL];                  // per-slice |k|^2 max
__device__ int g_qcnt[2 * NB];
__device__ int g_qlistP[NB * CAPQ], g_qlistS[NB * CAPQ];

__device__ __forceinline__ unsigned long long packf2(float lo, float hi) {
    return ((unsigned long long)__float_as_uint(hi) << 32) | (unsigned long long)__float_as_uint(lo);
}
__device__ __forceinline__ float lo32(unsigned long long v) { return __uint_as_float((unsigned)v); }
__device__ __forceinline__ float hi32(unsigned long long v) { return __uint_as_float((unsigned)(v >> 32)); }

// sm_103a packed fp32 pair math (PTX-only; per-lane rounding == scalar rn).
__device__ __forceinline__ unsigned long long mul2(unsigned long long a, unsigned long long b) {
    unsigned long long r;
    asm("mul.rn.f32x2 %0, %1, %2;" : "=l"(r) : "l"(a), "l"(b));
    return r;
}
__device__ __forceinline__ unsigned long long fma2(unsigned long long a, unsigned long long b, unsigned long long c) {
    unsigned long long r;
    asm("fma.rn.f32x2 %0, %1, %2, %3;" : "=l"(r) : "l"(a), "l"(b), "l"(c));
    return r;
}

__device__ __forceinline__ ulonglong2 ldcg_u2(const ulonglong2* p) {
    uint4 v = __ldcg((const uint4*)p);
    ulonglong2 r;
    r.x = ((unsigned long long)v.y << 32) | v.x;
    r.y = ((unsigned long long)v.w << 32) | v.z;
    return r;
}

#define PI_F 3.14159265358979f
#define TWO_PI_F 6.2831853071795865f

__device__ __forceinline__ unsigned qbins(float qpx, float qpy, float qsx, float qsy) {
    const float SC = NB / TWO_PI_F;
    int bP = (int)((atan2f(qpy, qpx) + PI_F) * SC);
    bP = min(max(bP, 0), NB - 1);
    int bS = (int)((atan2f(qsy, qsx) + PI_F) * SC);
    bS = min(max(bS, 0), NB - 1);
    return (unsigned)bP | ((unsigned)bS << 16);
}

__device__ __forceinline__ void push_query(int i, unsigned bp) {
    const int bP = (int)(bp & 0xffffu), bS = (int)(bp >> 16);
    int p = atomicAdd(&g_qcnt[bP], 1);
    if (p < CAPQ) g_qlistP[bP * CAPQ + p] = i;
    int s = atomicAdd(&g_qcnt[NB + bS], 1);
    if (s < CAPQ) g_qlistS[bS * CAPQ + s] = i;
}

// ---------------------------------------------------------------------------
// K1 (R14's, built from R4-proven proj shape + R12/R13-proven mechanics):
// 256 blocks x 128 thr x 32 rows. Projections, qlist push, per-bin partial
// maxes over this slice's 32 keys for ALL 128 bins (thread t = bin t, smem
// broadcast, rides in the DRAM shadow), per-slice |k|^2 max.
// ---------------------------------------------------------------------------
__global__ __launch_bounds__(K1TH) void proj_part_kernel(
        const float* __restrict__ emb,
        const float* __restrict__ wqp, const float* __restrict__ wkp,
        const float* __restrict__ wvop, const float* __restrict__ wvarg,
        const float* __restrict__ wqs, const float* __restrict__ wks,
        const float* __restrict__ wvs) {
    __shared__ float sw[11 * PD];
    __shared__ float se[RPS * PD];
    __shared__ ulonglong2 sKxy[RPS];

    const int blk = blockIdx.x;          // slice id 0..NSL-1
    const int tid = threadIdx.x;
    const float DLT = TWO_PI_F / NB;
    const int base = blk * RPS;

    if (tid < 2 * PD) {
        sw[tid]          = wqp[tid];
        sw[2 * PD + tid] = wkp[tid];
        sw[4 * PD + tid] = wqs[tid];
        sw[6 * PD + tid] = wks[tid];
    }
    if (tid < PD) {
        sw[8 * PD + tid]  = wvop[tid];
        sw[9 * PD + tid]  = wvarg[tid];
        sw[10 * PD + tid] = wvs[tid];
    }
    {
        const float4* emb4 = (const float4*)(emb + (size_t)base * PD);
#pragma unroll
        for (int v = 0; v < (RPS * PD / 4 + K1TH - 1) / K1TH; v++) {
            int idx = tid + v * K1TH;
            if (idx < RPS * PD / 4) ((float4*)se)[idx] = emb4[idx];
        }
    }
    __syncthreads();

    {
        const int row = tid >> 2, part = tid & 3;
        const float* r0 = se + row * PD + part * 9;
        float rv[9];
#pragma unroll
        for (int dd = 0; dd < 9; dd++) rv[dd] = r0[dd];
        // c: 0=Qp.x 1=Qp.y 2=Kp.x 3=Kp.y 4=Qs.x 5=Qs.y 6=Ks.x 7=Ks.y 8=Vop 9=Varg 10=Vstk
        float a[11];
#pragma unroll
        for (int c = 0; c < 11; c++) a[c] = 0.f;
#pragma unroll
        for (int c = 0; c < 11; c++) {
            const float* wc = sw + c * PD + part * 9;
#pragma unroll
            for (int dd = 0; dd < 9; dd++) a[c] = fmaf(rv[dd], wc[dd], a[c]);
        }
#pragma unroll
        for (int c = 0; c < 11; c++) {
            a[c] += __shfl_down_sync(0xffffffffu, a[c], 1);
            a[c] += __shfl_down_sync(0xffffffffu, a[c], 2);
        }
        if (part == 0) {
            int i = base + row;
            ulonglong2 kk = make_ulonglong2(packf2(a[2], a[6]), packf2(a[3], a[7]));
            g_QQ[i] = make_ulonglong2(packf2(a[0], a[4]), packf2(a[1], a[5]));
            g_KK[i] = kk;
            sKxy[row] = kk;
            unsigned bp = qbins(a[0], a[1], a[4], a[5]);
            g_binPS[i] = bp;
            g_Vop[i] = a[8]; g_Varg[i] = a[9]; g_Vstk[i] = a[10];
            push_query(i, bp);
        }
    }
    __syncthreads();

    // partials: thread tid == bin tid (128 bins). Same fma2/cosf bit
    // patterns K2 re-derives => the iff slice selection is lossless.
    {
        const float thc = -PI_F + (tid + 0.5f) * DLT;
        const float ux = cosf(thc), uy = sinf(thc);
        const unsigned long long ua = packf2(ux, ux), ub = packf2(uy, uy);
        float mP = -FLT_MAX, mS = -FLT_MAX;
#pragma unroll 4
        for (int k = 0; k < RPS; k++) {
            ulonglong2 kk = sKxy[k];
            unsigned long long s = fma2(ua, kk.x, mul2(ub, kk.y));
            mP = fmaxf(mP, lo32(s));
            mS = fmaxf(mS, hi32(s));
        }
        g_sPartP[tid * NSL + blk] = mP;
        g_sPartS[tid * NSL + blk] = mS;
    }
    if (tid < RPS) {
        ulonglong2 kk = sKxy[tid];
        unsigned long long n2 = fma2(kk.x, kk.x, mul2(kk.y, kk.y));
        float np = lo32(n2), ns = hi32(n2);
#pragma unroll
        for (int off = 16; off; off >>= 1) {
            np = fmaxf(np, __shfl_xor_sync(0xffffffffu, np, off));
            ns = fmaxf(ns, __shfl_xor_sync(0xffffffffu, ns, off));
        }
        if (tid == 0) { g_n2P[blk] = np; g_n2S[blk] = ns; }
    }
}

// ---------------------------------------------------------------------------
// K2: one block per bin, 512 threads. All fallbacks CHEAP (bounded cost).
//  R1: parallel loads (partials, n2, qcnt, qlists->smem).
//  ALU: threshold M - 1.25*Kmax*DLT (exact-cover, proven) + hot-slice
//       select (slice hot IFF partial >= thresh; lossless). No hot cap.
//  R2: scan hot-slice keys from global; candidates -> smem (K/V inline).
//  R3: resolve own queries (QQ parallel) vs smem candidates; exact fp32
//      scores + first-index tie-break.
//  qlist overflow (unreachable at CAPQ=2048) -> cheap binPS rescan resolve.
//  cand overflow (mathematically impossible) -> brute per query, bounded.
// ---------------------------------------------------------------------------
__global__ __launch_bounds__(K2TH) void bin_query_kernel(float* __restrict__ out, int T) {
    __shared__ float sPartP[NSL], sPartS[NSL];
    __shared__ int sHotP[NSL], sHotS[NSL];      // no cap: at most NSL entries
    __shared__ int sNhot[2];
    __shared__ int sqlP[CAPQ], sqlS[CAPQ];
    __shared__ float2 sCKP[CAP], sCKS[CAP];
    __shared__ float sCVop[CAP], sCVarg[CAP], sCVstk[CAP];
    __shared__ int scIdxP[CAP], scIdxS[CAP];
    __shared__ int scnt[2];
    __shared__ float sredM[16], sredN[16];
    __shared__ float sth[2];

    const int b = blockIdx.x;
    const int tid = threadIdx.x, lane = tid & 31, w = tid >> 5;
    const float DLT = TWO_PI_F / NB;
    const float thb = -PI_F + (b + 0.5f) * DLT;
    const float ux = cosf(thb), uy = sinf(thb);   // bit-identical to K1's bin b

    if (tid < 2) { scnt[tid] = 0; sNhot[tid] = 0; }

    // ===== R1: parallel independent loads =====
    const int totP = __ldcg(&g_qcnt[b]);
    const int totS = __ldcg(&g_qcnt[NB + b]);
    const int nqP = min(totP, CAPQ), nqS = min(totS, CAPQ);

    float myPart, myN2;   // warps 0-7: P slice tid; warps 8-15: S slice tid-256
    if (tid < NSL) {
        myPart = __ldcg(&g_sPartP[b * NSL + tid]);
        myN2   = __ldcg(&g_n2P[tid]);
        sPartP[tid] = myPart;
    } else {
        myPart = __ldcg(&g_sPartS[b * NSL + (tid - NSL)]);
        myN2   = __ldcg(&g_n2S[tid - NSL]);
        sPartS[tid - NSL] = myPart;
    }
    for (int t = tid; t < nqP; t += K2TH) sqlP[t] = __ldcg(&g_qlistP[b * CAPQ + t]);
    for (int t = tid; t < nqS; t += K2TH) sqlS[t] = __ldcg(&g_qlistS[b * CAPQ + t]);

    // reduce M and Kmax^2 per head (warps 0-7: P, warps 8-15: S)
    {
        float m = myPart, n = myN2;
#pragma unroll
        for (int off = 16; off; off >>= 1) {
            m = fmaxf(m, __shfl_xor_sync(0xffffffffu, m, off));
            n = fmaxf(n, __shfl_xor_sync(0xffffffffu, n, off));
        }
        if (lane == 0) { sredM[w] = m; sredN[w] = n; }
    }
    __syncthreads();
    if (tid == 0) {
        float MP = sredM[0], NP = sredN[0], MS = sredM[8], NS = sredN[8];
#pragma unroll
        for (int k = 1; k < 8; k++) {
            MP = fmaxf(MP, sredM[k]);     NP = fmaxf(NP, sredN[k]);
            MS = fmaxf(MS, sredM[8 + k]); NS = fmaxf(NS, sredN[8 + k]);
        }
        // Exact-cover threshold (proven R4/6/7/8/11/12): argmax key of any
        // direction in this bin has s_u >= M - Kmax*DLT; 1.25 absorbs fp slop.
        sth[0] = MP - 1.25f * sqrtf(NP) * DLT;
        sth[1] = MS - 1.25f * sqrtf(NS) * DLT;
    }
    __syncthreads();
    const float tP = sth[0], tS = sth[1];

    // hot-slice select (lossless iff); arrays sized NSL => no overflow
    if (tid < NSL) {
        if (sPartP[tid] >= tP) { int p = atomicAdd(&sNhot[0], 1); sHotP[p] = tid; }
    } else {
        if (sPartS[tid - NSL] >= tS) { int p = atomicAdd(&sNhot[1], 1); sHotS[p] = tid - NSL; }
    }
    __syncthreads();
    const int nbP = sNhot[0], nbS = sNhot[1];

    // ===== R2: scan hot slices from global; candidates -> smem =====
    for (int idx = tid; idx < nbP * RPS; idx += K2TH) {
        const int j = sHotP[idx >> 5] * RPS + (idx & (RPS - 1));
        ulonglong2 kk = ldcg_u2(&g_KK[j]);
        float kx = lo32(kk.x), ky = lo32(kk.y);
        float s = fmaf(ux, kx, __fmul_rn(uy, ky));   // == f32x2 lo lane
        if (s >= tP) {
            int p = atomicAdd(&scnt[0], 1);
            if (p < CAP) {
                scIdxP[p] = j;
                sCKP[p] = make_float2(kx, ky);
                sCVop[p] = __ldcg(&g_Vop[j]);
                sCVarg[p] = __ldcg(&g_Varg[j]);
            }
        }
    }
    for (int idx = tid; idx < nbS * RPS; idx += K2TH) {
        const int j = sHotS[idx >> 5] * RPS + (idx & (RPS - 1));
        ulonglong2 kk = ldcg_u2(&g_KK[j]);
        float kx = hi32(kk.x), ky = hi32(kk.y);
        float s = fmaf(ux, kx, __fmul_rn(uy, ky));   // == f32x2 hi lane
        if (s >= tS) {
            int p = atomicAdd(&scnt[1], 1);
            if (p < CAP) {
                scIdxS[p] = j;
                sCKS[p] = make_float2(kx, ky);
                sCVstk[p] = __ldcg(&g_Vstk[j]);
            }
        }
    }
    __syncthreads();
    const int nP = min(scnt[0], CAP), nS = min(scnt[1], CAP);
    const bool candOkP = (scnt[0] <= CAP), candOkS = (scnt[1] <= CAP);

    // ===== R3: resolve own queries =====
    if (candOkP) {
        if (totP <= CAPQ) {
            for (int t = tid; t < nqP; t += K2TH) {
                const int i = sqlP[t];
                ulonglong2 q = ldcg_u2(&g_QQ[i]);
                const float qx = lo32(q.x), qy = lo32(q.y);
                float best = -FLT_MAX; int bi = 0x7fffffff, bo = 0;
                for (int c = 0; c < nP; c++) {
                    float2 k = sCKP[c];
                    float sc = fmaf(qx, k.x, __fmul_rn(qy, k.y));
                    int kj = scIdxP[c];
                    if (sc > best || (sc == best && kj < bi)) { best = sc; bi = kj; bo = c; }
                }
                out[i]     = sCVop[bo];
                out[T + i] = sCVarg[bo];
            }
        } else {
            // CHEAP overflow fallback: rescan binPS, resolve vs smem cands
            for (int j = tid; j < T; j += K2TH) {
                if ((__ldcg(&g_binPS[j]) & 0xffffu) == (unsigned)b) {
                    ulonglong2 q = ldcg_u2(&g_QQ[j]);
                    const float qx = lo32(q.x), qy = lo32(q.y);
                    float best = -FLT_MAX; int bi = 0x7fffffff, bo = 0;
                    for (int c = 0; c < nP; c++) {
                        float2 k = sCKP[c];
                        float sc = fmaf(qx, k.x, __fmul_rn(qy, k.y));
                        int kj = scIdxP[c];
                        if (sc > best || (sc == best && kj < bi)) { best = sc; bi = kj; bo = c; }
                    }
                    out[j]     = sCVop[bo];
                    out[T + j] = sCVarg[bo];
                }
            }
        }
    } else {
        // candidate overflow (impossible): exact brute per query, bounded
        for (int j = tid; j < T; j += K2TH) {
            if ((__ldcg(&g_binPS[j]) & 0xffffu) == (unsigned)b) {
                ulonglong2 q = ldcg_u2(&g_QQ[j]);
                const float qx = lo32(q.x), qy = lo32(q.y);
                float best = -FLT_MAX; int bi = 0;
                for (int kj = 0; kj < T; kj++) {
                    ulonglong2 k2 = ldcg_u2(&g_KK[kj]);
                    float sc = fmaf(qx, lo32(k2.x), __fmul_rn(qy, lo32(k2.y)));
                    if (sc > best) { best = sc; bi = kj; }
                }
                out[j]     = __ldcg(&g_Vop[bi]);
                out[T + j] = __ldcg(&g_Varg[bi]);
            }
        }
    }
    if (candOkS) {
        if (totS <= CAPQ) {
            for (int t = tid; t < nqS; t += K2TH) {
                const int i = sqlS[t];
                ulonglong2 q = ldcg_u2(&g_QQ[i]);
                const float qx = hi32(q.x), qy = hi32(q.y);
                float best = -FLT_MAX; int bi = 0x7fffffff, bo = 0;
                for (int c = 0; c < nS; c++) {
                    float2 k = sCKS[c];
                    float sc = fmaf(qx, k.x, __fmul_rn(qy, k.y));
                    int kj = scIdxS[c];
                    if (sc > best || (sc == best && kj < bi)) { best = sc; bi = kj; bo = c; }
                }
                out[2 * T + i] = sCVstk[bo];
            }
        } else {
            for (int j = tid; j < T; j += K2TH) {
                if ((__ldcg(&g_binPS[j]) >> 16) == (unsigned)b) {
                    ulonglong2 q = ldcg_u2(&g_QQ[j]);
                    const float qx = hi32(q.x), qy = hi32(q.y);
                    float best = -FLT_MAX; int bi = 0x7fffffff, bo = 0;
                    for (int c = 0; c < nS; c++) {
                        float2 k = sCKS[c];
                        float sc = fmaf(qx, k.x, __fmul_rn(qy, k.y));
                        int kj = scIdxS[c];
                        if (sc > best || (sc == best && kj < bi)) { best = sc; bi = kj; bo = c; }
                    }
                    out[2 * T + j] = sCVstk[bo];
                }
            }
        }
    } else {
        for (int j = tid; j < T; j += K2TH) {
            if ((__ldcg(&g_binPS[j]) >> 16) == (unsigned)b) {
                ulonglong2 q = ldcg_u2(&g_QQ[j]);
                const float qx = hi32(q.x), qy = hi32(q.y);
                float best = -FLT_MAX; int bi = 0;
                for (int kj = 0; kj < T; kj++) {
                    ulonglong2 k2 = ldcg_u2(&g_KK[kj]);
                    float sc = fmaf(qx, hi32(k2.x), __fmul_rn(qy, hi32(k2.y)));
                    if (sc > best) { best = sc; bi = kj; }
                }
                out[2 * T + j] = __ldcg(&g_Vstk[bi]);
            }
        }
    }

    __syncthreads();
    if (tid == 0) { g_qcnt[b] = 0; g_qcnt[NB + b] = 0; }   // self-reset
}

// ---------------------------------------------------------------------------
// Generic fallback (D != 36 or T != MAXT): projection + brute-force argmax.
// ---------------------------------------------------------------------------
__global__ void proj_generic_kernel(
        const float* __restrict__ emb,
        const float* __restrict__ wqp, const float* __restrict__ wkp,
        const float* __restrict__ wvop, const float* __restrict__ wvarg,
        const float* __restrict__ wqs, const float* __restrict__ wks,
        const float* __restrict__ wvs, int T, int D) {
    extern __shared__ float sw[];
    const int tid = threadIdx.x;
    for (int k = tid; k < 2 * D; k += blockDim.x) {
        sw[k]         = wqp[k];
        sw[2 * D + k] = wkp[k];
        sw[4 * D + k] = wqs[k];
        sw[6 * D + k] = wks[k];
    }
    for (int k = tid; k < D; k += blockDim.x) {
        sw[8 * D + k]  = wvop[k];
        sw[9 * D + k]  = wvarg[k];
        sw[10 * D + k] = wvs[k];
    }
    __syncthreads();
    int i = blockIdx.x * blockDim.x + tid;
    if (i >= T) return;
    const float* e = emb + (size_t)i * D;
    float a[11];
#pragma unroll
    for (int c = 0; c < 11; c++) a[c] = 0.f;
    for (int d = 0; d < D; d++) {
        float ev = e[d];
#pragma unroll
        for (int c = 0; c < 11; c++) a[c] = fmaf(ev, sw[c * D + d], a[c]);
    }
    g_QQ[i] = make_ulonglong2(packf2(a[0], a[4]), packf2(a[1], a[5]));
    g_KK[i] = make_ulonglong2(packf2(a[2], a[6]), packf2(a[3], a[7]));
    g_Vop[i] = a[8]; g_Varg[i] = a[9]; g_Vstk[i] = a[10];
}

__global__ void brute_generic_kernel(float* __restrict__ out, int T) {
    const int gidx = blockIdx.x * blockDim.x + threadIdx.x;
    const int i = gidx >> 1, head = gidx & 1;
    if (i >= T) return;
    ulonglong2 q = g_QQ[i];
    const float qx = head ? hi32(q.x) : lo32(q.x);
    const float qy = head ? hi32(q.y) : lo32(q.y);
    float best = -FLT_MAX; int bi = 0;
    for (int j = 0; j < T; j++) {
        ulonglong2 k2 = g_KK[j];
        float kx = head ? hi32(k2.x) : lo32(k2.x);
        float ky = head ? hi32(k2.y) : lo32(k2.y);
        float sc = fmaf(qx, kx, __fmul_rn(qy, ky));
        if (sc > best) { best = sc; bi = j; }
    }
    if (head == 0) {
        out[i]     = g_Vop[bi];
        out[T + i] = g_Varg[bi];
    } else {
        out[2 * T + i] = g_Vstk[bi];
    }
}

extern "C" void kernel_launch(void* const* d_in, const int* in_sizes, int n_in,
                              void* d_out, int out_size) {
    const float* emb   = (const float*)d_in[0];
    const float* wqp   = (const float*)d_in[1];
    const float* wkp   = (const float*)d_in[2];
    const float* wvop  = (const float*)d_in[3];
    const float* wvarg = (const float*)d_in[4];
    const float* wqs   = (const float*)d_in[5];
    const float* wks   = (const float*)d_in[6];
    const float* wvs   = (const float*)d_in[7];
    float* out = (float*)d_out;

    const int D = in_sizes[1] / 2;   // WQ_prog is (2, D)
    const int T = in_sizes[0] / D;   // embeddings is (T, D)

    if (D == PD && T == MAXT) {
        proj_part_kernel<<<NSL, K1TH>>>(emb, wqp, wkp, wvop, wvarg, wqs, wks, wvs);
        bin_query_kernel<<<NB, K2TH>>>(out, T);
    } else {
        const int pb = (T + 255) / 256;
        proj_generic_kernel<<<pb, 256, (size_t)(11 * D) * sizeof(float)>>>(
            emb, wqp, wkp, wvop, wvarg, wqs, wks, wvs, T, D);
        brute_generic_kernel<<<(2 * T + 255) / 256, 256>>>(out, T);
    }
}